// round 11
// baseline (speedup 1.0000x reference)
#include <cuda_runtime.h>
#include <cuda_bf16.h>
#include <cstdint>

#define T_TOKENS 2048
#define DIM_     2048
#define HID_     5632
#define NEXP     8
#define NENT     (T_TOKENS * 2)

// ---------------------------------------------------------------------------
// Scratch (device globals — no cudaMalloc allowed)
// ---------------------------------------------------------------------------
__device__ int   g_eid [T_TOKENS][2];
__device__ float g_ew  [T_TOKENS][2];
__device__ int   g_pos [T_TOKENS][2];
__device__ int   g_list[NEXP][T_TOKENS];
__device__ int   g_cnt [NEXP];
__device__ int   g_off [NEXP];
__device__ __nv_bfloat16 g_xhi[(size_t)T_TOKENS * DIM_];
__device__ __nv_bfloat16 g_xlo[(size_t)T_TOKENS * DIM_];
__device__ __nv_bfloat16 g_hh [(size_t)NENT * HID_];
__device__ __nv_bfloat16 g_hl [(size_t)NENT * HID_];
__device__ float         g_y  [(size_t)NENT * DIM_];

// ---------------------------------------------------------------------------
// Helpers
// ---------------------------------------------------------------------------
__device__ __forceinline__ uint32_t smem_u32(const void* p) {
    uint32_t a;
    asm("{ .reg .u64 t; cvta.to.shared.u64 t, %1; cvt.u32.u64 %0, t; }" : "=r"(a) : "l"(p));
    return a;
}
__device__ __forceinline__ uint32_t pkbf(__nv_bfloat16 a, __nv_bfloat16 b) {
    return (uint32_t)__bfloat16_as_ushort(a) | ((uint32_t)__bfloat16_as_ushort(b) << 16);
}
__device__ __forceinline__ void split_pair(float f0, float f1, uint32_t& hp, uint32_t& lp) {
    __nv_bfloat16 h0 = __float2bfloat16(f0);
    __nv_bfloat16 h1 = __float2bfloat16(f1);
    __nv_bfloat16 l0 = __float2bfloat16(f0 - __bfloat162float(h0));
    __nv_bfloat16 l1 = __float2bfloat16(f1 - __bfloat162float(h1));
    hp = pkbf(h0, h1);
    lp = pkbf(l0, l1);
}

#define LDM_X4(r, addr)                                                          \
    asm volatile("ldmatrix.sync.aligned.m8n8.x4.shared.b16 {%0,%1,%2,%3}, [%4];" \
        : "=r"((r)[0]), "=r"((r)[1]), "=r"((r)[2]), "=r"((r)[3]) : "r"(addr))

#define MMA_BF16(d, a, b0, b1)                                                   \
    asm volatile("mma.sync.aligned.m16n8k16.row.col.f32.bf16.bf16.f32 "          \
        "{%0,%1,%2,%3}, {%4,%5,%6,%7}, {%8,%9}, {%0,%1,%2,%3};"                  \
        : "+f"((d)[0]), "+f"((d)[1]), "+f"((d)[2]), "+f"((d)[3])                 \
        : "r"((a)[0]), "r"((a)[1]), "r"((a)[2]), "r"((a)[3]), "r"(b0), "r"(b1))

#define CP_ASYNC16(dst, src)                                                     \
    asm volatile("cp.async.cg.shared.global [%0], [%1], 16;" :: "r"(dst), "l"(src))
#define CP_COMMIT() asm volatile("cp.async.commit_group;" ::: "memory")
#define CP_WAIT0()  asm volatile("cp.async.wait_group 0;" ::: "memory")
#define CP_WAIT1()  asm volatile("cp.async.wait_group 1;" ::: "memory")

// A smem: rows of 32 bf16 padded to 80B -> conflict-free ldmatrix (proven R4-R10)
#define ROWB    80
#define TILE_A  10240           // 128 rows * 80B (one A matrix: hi or lo)
#define OFF_AH  0
#define OFF_AL  10240
// ffn1 B: two fp32 tiles [32 k][64+4 pad floats]: w1 and w3
#define B1PITCH 272             // 68 floats
#define OFF_B1  20480
#define OFF_B3  (20480 + 32 * 272 + 16)   // +16B -> distinct banks for odd-parity lanes
#define F1_STAGE (OFF_B3 + 32 * 272)      // 37904
#define F1_SMEM  (3 * F1_STAGE)           // 113712; x2 CTAs = 227424 <= 228KB
// ffn2 B: one fp32 tile [32 k][128+4 pad floats]
#define B2PITCH 528             // 132 floats
#define OFF_B2  20480
#define F2_STAGE (OFF_B2 + 32 * 528)      // 37376
#define F2_SMEM  (3 * F2_STAGE)           // 112128

// ---------------------------------------------------------------------------
// Gating + routing + x split
// ---------------------------------------------------------------------------
__global__ void gate_kernel(const float* __restrict__ x, const float* __restrict__ gw) {
    const int t = blockIdx.x, lane = threadIdx.x & 31, w = threadIdx.x >> 5;
    const float* xr = x + (size_t)t * DIM_;
    const float* gr = gw + (size_t)w * DIM_;
    float s = 0.f;
    for (int d = lane * 4; d < DIM_; d += 128) {
        float4 a = *(const float4*)(xr + d);
        float4 b = *(const float4*)(gr + d);
        s += a.x * b.x + a.y * b.y + a.z * b.z + a.w * b.w;
    }
    #pragma unroll
    for (int o = 16; o; o >>= 1) s += __shfl_xor_sync(0xffffffffu, s, o);
    __shared__ float sc[NEXP];
    if (lane == 0) sc[w] = s;
    __syncthreads();
    if (threadIdx.x == 0) {
        int b0 = 0; float s0 = sc[0];
        #pragma unroll
        for (int e = 1; e < NEXP; e++) if (sc[e] > s0) { s0 = sc[e]; b0 = e; }
        int b1 = -1; float s1 = -1e30f;
        #pragma unroll
        for (int e = 0; e < NEXP; e++) if (e != b0 && sc[e] > s1) { s1 = sc[e]; b1 = e; }
        float e1 = __expf(s1 - s0);
        float inv = 1.f / (1.f + e1);
        g_eid[t][0] = b0; g_eid[t][1] = b1;
        g_ew [t][0] = inv; g_ew [t][1] = e1 * inv;
    }
}

__global__ void route_kernel() {
    const int lane = threadIdx.x & 31, e = threadIdx.x >> 5;
    if (e < NEXP) {
        int cnt = 0;
        for (int t0 = 0; t0 < T_TOKENS; t0 += 32) {
            int t = t0 + lane;
            int e0 = g_eid[t][0], e1 = g_eid[t][1];
            bool sel = (e0 == e) || (e1 == e);
            int slot = (e0 == e) ? 0 : 1;
            unsigned m = __ballot_sync(0xffffffffu, sel);
            if (sel) {
                int p = cnt + __popc(m & ((1u << lane) - 1u));
                g_list[e][p] = t;
                g_pos[t][slot] = p;
            }
            cnt += __popc(m);
        }
        if (lane == 0) g_cnt[e] = cnt;
    }
    __syncthreads();
    if (threadIdx.x == 0) {
        int off = 0;
        #pragma unroll
        for (int i = 0; i < NEXP; i++) { g_off[i] = off; off += g_cnt[i]; }
    }
}

__global__ void split_x_kernel(const float* __restrict__ x) {
    int i = blockIdx.x * blockDim.x + threadIdx.x;
    float4 v = ((const float4*)x)[i];
    size_t o = (size_t)i * 4;
    float vv[4] = {v.x, v.y, v.z, v.w};
    #pragma unroll
    for (int k = 0; k < 4; k++) {
        __nv_bfloat16 h = __float2bfloat16(vv[k]);
        g_xhi[o + k] = h;
        g_xlo[o + k] = __float2bfloat16(vv[k] - __bfloat162float(h));
    }
}

// ---------------------------------------------------------------------------
// GEMM1: u = x@w1, v = x@w3 (3-term bf16 split), h = silu(u)*v
// 256 threads = 8 warps (2m x 4n), warp tile 64x32 over 128 interleaved B cols.
// A: cp.async bf16 hi/lo + ldmatrix. B: cp.async fp32 [k][n] tiles (w1,w3),
// fragments built by per-lane LDS + in-register split. 3-stage pipeline,
// wait_group(1): every copy has ~2 iterations of slack.
// ---------------------------------------------------------------------------
__global__ void __launch_bounds__(256, 2) ffn1_kernel(const float* __restrict__ w1,
                                                      const float* __restrict__ w3) {
    const int e   = blockIdx.z;
    const int cnt = g_cnt[e];
    const int m0  = blockIdx.x * 128;
    if (m0 >= cnt) return;
    const int n0   = blockIdx.y * 64;     // h-cols
    const int base = g_off[e];

    extern __shared__ char sm[];
    const uint32_t sbase = smem_u32(sm);
    const int tid = threadIdx.x, lane = tid & 31, wid = tid >> 5;
    const int wm = wid & 1, wn = wid >> 1;

    const float* w1e = w1 + (size_t)e * DIM_ * HID_;
    const float* w3e = w3 + (size_t)e * DIM_ * HID_;

    // A loader: 1024 chunks (2 mats x 128 rows x 4 kq), 4/thread
    const __nv_bfloat16* apA[4];
    uint32_t aoA[4];
    #pragma unroll
    for (int q = 0; q < 4; q++) {
        int idx = tid + q * 256;
        int mat = idx >> 9;
        int rem = idx & 511;
        int row = rem >> 2, kq = rem & 3;
        int tok = g_list[e][min(m0 + row, cnt - 1)];
        apA[q] = (mat ? g_xlo : g_xhi) + (size_t)tok * DIM_ + kq * 8;
        aoA[q] = mat * TILE_A + row * ROWB + kq * 16;
    }
    // B loader: 1024 chunks (2 mats x 32 k-rows x 16 n-quads), 4/thread, coalesced
    const float* bpB[4];
    uint32_t boB[4];
    #pragma unroll
    for (int q = 0; q < 4; q++) {
        int c = tid + q * 256;
        int m = c >> 9;
        int rem = c & 511;
        int krow = rem >> 4;
        int nq = rem & 15;
        bpB[q] = (m ? w3e : w1e) + (size_t)krow * HID_ + (n0 + nq * 4);
        boB[q] = (m ? OFF_B3 : OFF_B1) + krow * B1PITCH + nq * 16;
    }

    const int mi = lane >> 3, lr = lane & 7;
    const uint32_t aLB = (uint32_t)((wm * 64 + (mi & 1) * 8 + lr) * ROWB + (mi >> 1) * 16);

    float acc[4][4][4];
    #pragma unroll
    for (int a = 0; a < 4; a++)
        #pragma unroll
        for (int b = 0; b < 4; b++)
            #pragma unroll
            for (int c = 0; c < 4; c++) acc[a][b][c] = 0.f;

    const int NCH = DIM_ / 32;   // 64
    // prologue: stages 0,1
    #pragma unroll
    for (int s = 0; s < 2; s++) {
        uint32_t stg = sbase + s * F1_STAGE;
        int kk = s * 32;
        #pragma unroll
        for (int q = 0; q < 4; q++) CP_ASYNC16(stg + aoA[q], apA[q] + kk);
        #pragma unroll
        for (int q = 0; q < 4; q++) CP_ASYNC16(stg + boB[q], bpB[q] + (size_t)kk * HID_);
        CP_COMMIT();
    }

    // per-lane B fragment source (fp32 column pointers)
    const int rB = lane >> 2;                 // 0..7 : n' offset within n8
    const int klB = (lane & 3) * 2;           // k pair base within k16

    for (int i = 0; i < NCH; i++) {
        if (i == NCH - 1) { CP_WAIT0(); } else { CP_WAIT1(); }
        __syncthreads();
        if (i + 2 < NCH) {
            uint32_t stg = sbase + ((i + 2) % 3) * F1_STAGE;
            int kk = (i + 2) * 32;
            #pragma unroll
            for (int q = 0; q < 4; q++) CP_ASYNC16(stg + aoA[q], apA[q] + kk);
            #pragma unroll
            for (int q = 0; q < 4; q++) CP_ASYNC16(stg + boB[q], bpB[q] + (size_t)kk * HID_);
            CP_COMMIT();
        }
        const int sc = i % 3;
        const uint32_t stS = sbase + sc * F1_STAGE;
        const char* stC = sm + sc * F1_STAGE;
        const char* bb  = stC + ((rB & 1) ? OFF_B3 : OFF_B1);

        #pragma unroll
        for (int ks = 0; ks < 2; ks++) {
            const int kl = ks * 16 + klB;
            uint32_t b0h[4], b0l[4], b1h[4], b1l[4];
            #pragma unroll
            for (int nt = 0; nt < 4; nt++) {
                const float* pc = (const float*)(bb + (wn * 16 + nt * 4 + (rB >> 1)) * 4);
                float f0 = pc[(size_t)kl * 68];
                float f1 = pc[(size_t)(kl + 1) * 68];
                float f2 = pc[(size_t)(kl + 8) * 68];
                float f3 = pc[(size_t)(kl + 9) * 68];
                split_pair(f0, f1, b0h[nt], b0l[nt]);
                split_pair(f2, f3, b1h[nt], b1l[nt]);
            }
            #pragma unroll
            for (int mt = 0; mt < 4; mt++) {
                uint32_t ah[4], al[4];
                LDM_X4(ah, stS + OFF_AH + aLB + mt * (16 * ROWB) + ks * 32);
                LDM_X4(al, stS + OFF_AL + aLB + mt * (16 * ROWB) + ks * 32);
                #pragma unroll
                for (int nt = 0; nt < 4; nt++) {
                    MMA_BF16(acc[mt][nt], ah, b0h[nt], b1h[nt]);
                    MMA_BF16(acc[mt][nt], al, b0h[nt], b1h[nt]);
                    MMA_BF16(acc[mt][nt], ah, b0l[nt], b1l[nt]);
                }
            }
        }
    }

    // epilogue: d0=u, d1=v for the same h-col, in-register SwiGLU
    #pragma unroll
    for (int mt = 0; mt < 4; mt++)
        #pragma unroll
        for (int nt = 0; nt < 4; nt++) {
            int j = wn * 16 + nt * 4 + (lane & 3);   // h-col within 64
            #pragma unroll
            for (int rr = 0; rr < 2; rr++) {
                int r  = wm * 64 + mt * 16 + (lane >> 2) + rr * 8;
                int gm = m0 + r;
                float u = acc[mt][nt][2*rr], v = acc[mt][nt][2*rr+1];
                float h = u / (1.f + __expf(-u)) * v;
                __nv_bfloat16 hh = __float2bfloat16(h);
                __nv_bfloat16 hl = __float2bfloat16(h - __bfloat162float(hh));
                if (gm < cnt) {
                    size_t dst = (size_t)(base + gm) * HID_ + n0 + j;
                    g_hh[dst] = hh;
                    g_hl[dst] = hl;
                }
            }
        }
}

// ---------------------------------------------------------------------------
// GEMM2: y = h @ w2 (3-term split). 256 threads (2m x 4n), warp 64x32,
// CTA 128 x 128. Same 3-stage all-cp.async pipeline; B fp32 tile [k][n].
// ---------------------------------------------------------------------------
__global__ void __launch_bounds__(256, 2) ffn2_kernel(const float* __restrict__ w2) {
    const int e   = blockIdx.z;
    const int cnt = g_cnt[e];
    const int m0  = blockIdx.x * 128;
    if (m0 >= cnt) return;
    const int n0   = blockIdx.y * 128;
    const int base = g_off[e];

    extern __shared__ char sm[];
    const uint32_t sbase = smem_u32(sm);
    const int tid = threadIdx.x, lane = tid & 31, wid = tid >> 5;
    const int wm = wid & 1, wn = wid >> 1;

    const float* w2e = w2 + (size_t)e * HID_ * DIM_;

    const __nv_bfloat16* apA[4];
    uint32_t aoA[4];
    #pragma unroll
    for (int q = 0; q < 4; q++) {
        int idx = tid + q * 256;
        int mat = idx >> 9;
        int rem = idx & 511;
        int row = rem >> 2, kq = rem & 3;
        int r   = base + min(m0 + row, cnt - 1);
        apA[q] = (mat ? g_hl : g_hh) + (size_t)r * HID_ + kq * 8;
        aoA[q] = mat * TILE_A + row * ROWB + kq * 16;
    }
    const float* bpB[4];
    uint32_t boB[4];
    #pragma unroll
    for (int q = 0; q < 4; q++) {
        int c = tid + q * 256;
        int krow = c >> 5;
        int nq = c & 31;
        bpB[q] = w2e + (size_t)krow * DIM_ + (n0 + nq * 4);
        boB[q] = OFF_B2 + krow * B2PITCH + nq * 16;
    }

    const int mi = lane >> 3, lr = lane & 7;
    const uint32_t aLB = (uint32_t)((wm * 64 + (mi & 1) * 8 + lr) * ROWB + (mi >> 1) * 16);

    float acc[4][4][4];
    #pragma unroll
    for (int a = 0; a < 4; a++)
        #pragma unroll
        for (int b = 0; b < 4; b++)
            #pragma unroll
            for (int c = 0; c < 4; c++) acc[a][b][c] = 0.f;

    const int NCH = HID_ / 32;   // 176
    #pragma unroll
    for (int s = 0; s < 2; s++) {
        uint32_t stg = sbase + s * F2_STAGE;
        int kk = s * 32;
        #pragma unroll
        for (int q = 0; q < 4; q++) CP_ASYNC16(stg + aoA[q], apA[q] + kk);
        #pragma unroll
        for (int q = 0; q < 4; q++) CP_ASYNC16(stg + boB[q], bpB[q] + (size_t)kk * DIM_);
        CP_COMMIT();
    }

    const int rB = lane >> 2;
    const int klB = (lane & 3) * 2;

    for (int i = 0; i < NCH; i++) {
        if (i == NCH - 1) { CP_WAIT0(); } else { CP_WAIT1(); }
        __syncthreads();
        if (i + 2 < NCH) {
            uint32_t stg = sbase + ((i + 2) % 3) * F2_STAGE;
            int kk = (i + 2) * 32;
            #pragma unroll
            for (int q = 0; q < 4; q++) CP_ASYNC16(stg + aoA[q], apA[q] + kk);
            #pragma unroll
            for (int q = 0; q < 4; q++) CP_ASYNC16(stg + boB[q], bpB[q] + (size_t)kk * DIM_);
            CP_COMMIT();
        }
        const int sc = i % 3;
        const uint32_t stS = sbase + sc * F2_STAGE;
        const char* stC = sm + sc * F2_STAGE;

        #pragma unroll
        for (int ks = 0; ks < 2; ks++) {
            const int kl = ks * 16 + klB;
            uint32_t b0h[4], b0l[4], b1h[4], b1l[4];
            #pragma unroll
            for (int nt = 0; nt < 4; nt++) {
                const float* pc = (const float*)(stC + OFF_B2 + (wn * 32 + nt * 8 + rB) * 4);
                float f0 = pc[(size_t)kl * 132];
                float f1 = pc[(size_t)(kl + 1) * 132];
                float f2 = pc[(size_t)(kl + 8) * 132];
                float f3 = pc[(size_t)(kl + 9) * 132];
                split_pair(f0, f1, b0h[nt], b0l[nt]);
                split_pair(f2, f3, b1h[nt], b1l[nt]);
            }
            #pragma unroll
            for (int mt = 0; mt < 4; mt++) {
                uint32_t ah[4], al[4];
                LDM_X4(ah, stS + OFF_AH + aLB + mt * (16 * ROWB) + ks * 32);
                LDM_X4(al, stS + OFF_AL + aLB + mt * (16 * ROWB) + ks * 32);
                #pragma unroll
                for (int nt = 0; nt < 4; nt++) {
                    MMA_BF16(acc[mt][nt], ah, b0h[nt], b1h[nt]);
                    MMA_BF16(acc[mt][nt], al, b0h[nt], b1h[nt]);
                    MMA_BF16(acc[mt][nt], ah, b0l[nt], b1l[nt]);
                }
            }
        }
    }

    #pragma unroll
    for (int mt = 0; mt < 4; mt++)
        #pragma unroll
        for (int nt = 0; nt < 4; nt++) {
            int c = wn * 32 + nt * 8 + (lane & 3) * 2;
            #pragma unroll
            for (int rr = 0; rr < 2; rr++) {
                int r  = wm * 64 + mt * 16 + (lane >> 2) + rr * 8;
                int gm = m0 + r;
                if (gm < cnt) {
                    size_t dst = (size_t)(base + gm) * DIM_ + n0 + c;
                    *(float2*)(g_y + dst) = make_float2(acc[mt][nt][2*rr], acc[mt][nt][2*rr+1]);
                }
            }
        }
}

// ---------------------------------------------------------------------------
// Combine
// ---------------------------------------------------------------------------
__global__ void combine_kernel(float* __restrict__ out) {
    const int t  = blockIdx.x;
    const int e0 = g_eid[t][0];
    const int e1 = g_eid[t][1];
    const int n0 = g_off[e0] + g_pos[t][0];
    const int n1 = g_off[e1] + g_pos[t][1];
    const float w0 = g_ew[t][0];
    const float w1 = g_ew[t][1];
    const float* y0 = &g_y[(size_t)n0 * DIM_];
    const float* y1 = &g_y[(size_t)n1 * DIM_];
    float* op = out + (size_t)t * DIM_;
    for (int d = threadIdx.x * 4; d < DIM_; d += blockDim.x * 4) {
        float4 a = *(const float4*)(y0 + d);
        float4 b = *(const float4*)(y1 + d);
        *(float4*)(op + d) = make_float4(w0 * a.x + w1 * b.x, w0 * a.y + w1 * b.y,
                                         w0 * a.z + w1 * b.z, w0 * a.w + w1 * b.w);
    }
}

// ---------------------------------------------------------------------------
// Entry point
// ---------------------------------------------------------------------------
extern "C" void kernel_launch(void* const* d_in, const int* in_sizes, int n_in,
                              void* d_out, int out_size) {
    const float* x  = (const float*)d_in[0];
    const float* gw = (const float*)d_in[1];
    const float* w1 = (const float*)d_in[2];
    const float* w2 = (const float*)d_in[3];
    const float* w3 = (const float*)d_in[4];
    float* out = (float*)d_out;

    cudaFuncSetAttribute(ffn1_kernel, cudaFuncAttributeMaxDynamicSharedMemorySize, F1_SMEM);
    cudaFuncSetAttribute(ffn2_kernel, cudaFuncAttributeMaxDynamicSharedMemorySize, F2_SMEM);

    gate_kernel<<<T_TOKENS, 256>>>(x, gw);
    route_kernel<<<1, 256>>>();
    split_x_kernel<<<(T_TOKENS * DIM_ / 4) / 256, 256>>>(x);
    ffn1_kernel<<<dim3(T_TOKENS / 128, HID_ / 64, NEXP), 256, F1_SMEM>>>(w1, w3);
    ffn2_kernel<<<dim3(T_TOKENS / 128, DIM_ / 128, NEXP), 256, F2_SMEM>>>(w2);
    combine_kernel<<<T_TOKENS, 256>>>(out);
}

// round 12
// speedup vs baseline: 1.1336x; 1.1336x over previous
#include <cuda_runtime.h>
#include <cuda_bf16.h>
#include <cstdint>

#define T_TOKENS 2048
#define DIM_     2048
#define HID_     5632
#define NEXP     8
#define NENT     (T_TOKENS * 2)

// ---------------------------------------------------------------------------
// Scratch (device globals — no cudaMalloc allowed)
// ---------------------------------------------------------------------------
__device__ int   g_eid [T_TOKENS][2];
__device__ float g_ew  [T_TOKENS][2];
__device__ int   g_pos [T_TOKENS][2];
__device__ int   g_list[NEXP][T_TOKENS];
__device__ int   g_cnt [NEXP];
__device__ int   g_off [NEXP];
__device__ __nv_bfloat16 g_xhi[(size_t)T_TOKENS * DIM_];
__device__ __nv_bfloat16 g_xlo[(size_t)T_TOKENS * DIM_];
__device__ __nv_bfloat16 g_hh [(size_t)NENT * HID_];
__device__ __nv_bfloat16 g_hl [(size_t)NENT * HID_];
__device__ float         g_y  [(size_t)NENT * DIM_];

// ---------------------------------------------------------------------------
// Helpers
// ---------------------------------------------------------------------------
__device__ __forceinline__ uint32_t smem_u32(const void* p) {
    uint32_t a;
    asm("{ .reg .u64 t; cvta.to.shared.u64 t, %1; cvt.u32.u64 %0, t; }" : "=r"(a) : "l"(p));
    return a;
}
__device__ __forceinline__ uint32_t pkbf(__nv_bfloat16 a, __nv_bfloat16 b) {
    return (uint32_t)__bfloat16_as_ushort(a) | ((uint32_t)__bfloat16_as_ushort(b) << 16);
}
__device__ __forceinline__ void split_pair(float f0, float f1, uint32_t& hp, uint32_t& lp) {
    __nv_bfloat16 h0 = __float2bfloat16(f0);
    __nv_bfloat16 h1 = __float2bfloat16(f1);
    __nv_bfloat16 l0 = __float2bfloat16(f0 - __bfloat162float(h0));
    __nv_bfloat16 l1 = __float2bfloat16(f1 - __bfloat162float(h1));
    hp = pkbf(h0, h1);
    lp = pkbf(l0, l1);
}

#define LDM_X4(r, addr)                                                          \
    asm volatile("ldmatrix.sync.aligned.m8n8.x4.shared.b16 {%0,%1,%2,%3}, [%4];" \
        : "=r"((r)[0]), "=r"((r)[1]), "=r"((r)[2]), "=r"((r)[3]) : "r"(addr))

#define MMA_BF16(d, a, b0, b1)                                                   \
    asm volatile("mma.sync.aligned.m16n8k16.row.col.f32.bf16.bf16.f32 "          \
        "{%0,%1,%2,%3}, {%4,%5,%6,%7}, {%8,%9}, {%0,%1,%2,%3};"                  \
        : "+f"((d)[0]), "+f"((d)[1]), "+f"((d)[2]), "+f"((d)[3])                 \
        : "r"((a)[0]), "r"((a)[1]), "r"((a)[2]), "r"((a)[3]), "r"(b0), "r"(b1))

#define CP_ASYNC16(dst, src)                                                     \
    asm volatile("cp.async.cg.shared.global [%0], [%1], 16;" :: "r"(dst), "l"(src))
#define CP_COMMIT() asm volatile("cp.async.commit_group;" ::: "memory")
#define CP_WAIT0()  asm volatile("cp.async.wait_group 0;" ::: "memory")
#define CP_WAIT1()  asm volatile("cp.async.wait_group 1;" ::: "memory")

// bf16 tiles: rows of 32 bf16 padded to 80B -> conflict-free ldmatrix (R4-R9)
#define ROWB     80
#define TILE_A   10240          // 128 rows * 80B (one A matrix: hi or lo)
#define OFF_AH   0
#define OFF_AL   10240
#define OFF_BH   20480          // B: 128 rows * 80B per matrix
#define OFF_BL   30720
#define STAGE_BF 40960          // one bf16 stage (A hi/lo + B hi/lo)
// fp32 B staging: 32 k-rows x 128 floats (512B pitch), double-buffered
#define OFF_STG  81920
#define STG_SZ   16384
#define SMEM_TOT 114688         // = 14*8192 exactly; 2 CTAs/SM

// ---------------------------------------------------------------------------
// Gating + routing + x split
// ---------------------------------------------------------------------------
__global__ void gate_kernel(const float* __restrict__ x, const float* __restrict__ gw) {
    const int t = blockIdx.x, lane = threadIdx.x & 31, w = threadIdx.x >> 5;
    const float* xr = x + (size_t)t * DIM_;
    const float* gr = gw + (size_t)w * DIM_;
    float s = 0.f;
    for (int d = lane * 4; d < DIM_; d += 128) {
        float4 a = *(const float4*)(xr + d);
        float4 b = *(const float4*)(gr + d);
        s += a.x * b.x + a.y * b.y + a.z * b.z + a.w * b.w;
    }
    #pragma unroll
    for (int o = 16; o; o >>= 1) s += __shfl_xor_sync(0xffffffffu, s, o);
    __shared__ float sc[NEXP];
    if (lane == 0) sc[w] = s;
    __syncthreads();
    if (threadIdx.x == 0) {
        int b0 = 0; float s0 = sc[0];
        #pragma unroll
        for (int e = 1; e < NEXP; e++) if (sc[e] > s0) { s0 = sc[e]; b0 = e; }
        int b1 = -1; float s1 = -1e30f;
        #pragma unroll
        for (int e = 0; e < NEXP; e++) if (e != b0 && sc[e] > s1) { s1 = sc[e]; b1 = e; }
        float e1 = __expf(s1 - s0);
        float inv = 1.f / (1.f + e1);
        g_eid[t][0] = b0; g_eid[t][1] = b1;
        g_ew [t][0] = inv; g_ew [t][1] = e1 * inv;
    }
}

__global__ void route_kernel() {
    const int lane = threadIdx.x & 31, e = threadIdx.x >> 5;
    if (e < NEXP) {
        int cnt = 0;
        for (int t0 = 0; t0 < T_TOKENS; t0 += 32) {
            int t = t0 + lane;
            int e0 = g_eid[t][0], e1 = g_eid[t][1];
            bool sel = (e0 == e) || (e1 == e);
            int slot = (e0 == e) ? 0 : 1;
            unsigned m = __ballot_sync(0xffffffffu, sel);
            if (sel) {
                int p = cnt + __popc(m & ((1u << lane) - 1u));
                g_list[e][p] = t;
                g_pos[t][slot] = p;
            }
            cnt += __popc(m);
        }
        if (lane == 0) g_cnt[e] = cnt;
    }
    __syncthreads();
    if (threadIdx.x == 0) {
        int off = 0;
        #pragma unroll
        for (int i = 0; i < NEXP; i++) { g_off[i] = off; off += g_cnt[i]; }
    }
}

__global__ void split_x_kernel(const float* __restrict__ x) {
    int i = blockIdx.x * blockDim.x + threadIdx.x;
    float4 v = ((const float4*)x)[i];
    size_t o = (size_t)i * 4;
    float vv[4] = {v.x, v.y, v.z, v.w};
    #pragma unroll
    for (int k = 0; k < 4; k++) {
        __nv_bfloat16 h = __float2bfloat16(vv[k]);
        g_xhi[o + k] = h;
        g_xlo[o + k] = __float2bfloat16(vv[k] - __bfloat162float(h));
    }
}

// ---------------------------------------------------------------------------
// GEMM1: u = x@w1, v = x@w3 (3-term bf16 split), h = silu(u)*v
// 256 threads = 8 warps (2m x 4n), warp tile 64x32, CTA 128 x 64 h-cols
// (128 interleaved B rows). B weights: cp.async fp32 -> staging (2 chunks
// ahead) -> LDS+convert+STS into next stage's bf16 tile (no global latency
// on the barrier path). A: cp.async bf16 at distance 1. One barrier/iter.
// ---------------------------------------------------------------------------
__global__ void __launch_bounds__(256, 2) ffn1_kernel(const float* __restrict__ w1,
                                                      const float* __restrict__ w3) {
    const int e   = blockIdx.z;
    const int cnt = g_cnt[e];
    const int m0  = blockIdx.x * 128;
    if (m0 >= cnt) return;
    const int n0   = blockIdx.y * 64;     // h-cols
    const int base = g_off[e];

    extern __shared__ char sm[];
    const uint32_t sbase = smem_u32(sm);
    const int tid = threadIdx.x, lane = tid & 31, wid = tid >> 5;
    const int wm = wid & 1, wn = wid >> 1;

    const float* w1e = w1 + (size_t)e * DIM_ * HID_;
    const float* w3e = w3 + (size_t)e * DIM_ * HID_;

    // A loader: 1024 chunks (2 mats x 128 rows x 4 kq), 4/thread
    const __nv_bfloat16* apA[4];
    uint32_t aoA[4];
    #pragma unroll
    for (int q = 0; q < 4; q++) {
        int idx = tid + q * 256;
        int mat = idx >> 9;
        int rem = idx & 511;
        int row = rem >> 2, kq = rem & 3;
        int tok = g_list[e][min(m0 + row, cnt - 1)];
        apA[q] = (mat ? g_xlo : g_xhi) + (size_t)tok * DIM_ + kq * 8;
        aoA[q] = mat * TILE_A + row * ROWB + kq * 16;
    }
    // Staging cp loader: 1024 16B-chunks (32 k x 2 mats x 16 quads), 4/thread
    const float* spB[4];
    uint32_t soB[4];
    #pragma unroll
    for (int q = 0; q < 4; q++) {
        int c = tid + q * 256;
        int kr = c >> 5;
        int rem = c & 31;
        int mat = rem >> 4;
        int nq = rem & 15;
        spB[q] = (mat ? w3e : w1e) + (size_t)kr * HID_ + (n0 + nq * 4);
        soB[q] = OFF_STG + kr * 512 + mat * 256 + nq * 16;
    }
    // Converter: 512 tasks (128 interleaved rows x 4 k-blocks), 2/thread
    int cvSrc[2];     // float index base in staging (add kk*128)
    uint32_t cvDst[2];// byte offset within stage (add OFF_BH/OFF_BL)
    #pragma unroll
    for (int r = 0; r < 2; r++) {
        int task = tid + r * 256;
        int np = task & 127;
        int kb = task >> 7;
        cvSrc[r] = kb * 8 * 128 + (np & 1) * 64 + (np >> 1);
        cvDst[r] = np * ROWB + kb * 16;
    }

    const int mi = lane >> 3, lr = lane & 7;
    const uint32_t aLB = (uint32_t)((wm * 64 + (mi & 1) * 8 + lr) * ROWB + (mi >> 1) * 16);
    const uint32_t bLB = (uint32_t)((wn * 32 + (mi >> 1) * 8 + lr) * ROWB + (mi & 1) * 16);

    float acc[4][4][4];
    #pragma unroll
    for (int a = 0; a < 4; a++)
        #pragma unroll
        for (int b = 0; b < 4; b++)
            #pragma unroll
            for (int c = 0; c < 4; c++) acc[a][b][c] = 0.f;

    const int NCH = DIM_ / 32;   // 64
    // prologue: A(0)+S(0) as group1; S(1) as group2
    #pragma unroll
    for (int q = 0; q < 4; q++) CP_ASYNC16(sbase + aoA[q], apA[q]);
    #pragma unroll
    for (int q = 0; q < 4; q++) CP_ASYNC16(sbase + soB[q], spB[q]);
    CP_COMMIT();
    #pragma unroll
    for (int q = 0; q < 4; q++) CP_ASYNC16(sbase + soB[q] + STG_SZ, spB[q] + (size_t)32 * HID_);
    CP_COMMIT();
    CP_WAIT1();
    __syncthreads();
    // convert chunk 0: staging0 -> B tile of stage 0
    #pragma unroll
    for (int r = 0; r < 2; r++) {
        const float* sf = (const float*)(sm + OFF_STG) + cvSrc[r];
        float f[8];
        #pragma unroll
        for (int kk = 0; kk < 8; kk++) f[kk] = sf[kk * 128];
        uint32_t hp[4], lp[4];
        #pragma unroll
        for (int j = 0; j < 4; j++) split_pair(f[2*j], f[2*j+1], hp[j], lp[j]);
        *(uint4*)(sm + OFF_BH + cvDst[r]) = make_uint4(hp[0], hp[1], hp[2], hp[3]);
        *(uint4*)(sm + OFF_BL + cvDst[r]) = make_uint4(lp[0], lp[1], lp[2], lp[3]);
    }
    CP_WAIT0();
    __syncthreads();

    for (int i = 0; i < NCH; i++) {
        const int s = i & 1;
        const uint32_t stS = sbase + s * STAGE_BF;
        // issue copies: A(i+1) into other stage; staging chunk i+2 into buf s
        if (i + 1 < NCH) {
            int kk = (i + 1) * 32;
            #pragma unroll
            for (int q = 0; q < 4; q++)
                CP_ASYNC16(sbase + (1 - s) * STAGE_BF + aoA[q], apA[q] + kk);
        }
        if (i + 2 < NCH) {
            size_t kk = (size_t)(i + 2) * 32;
            #pragma unroll
            for (int q = 0; q < 4; q++)
                CP_ASYNC16(sbase + soB[q] + s * STG_SZ, spB[q] + kk * HID_);
        }
        CP_COMMIT();
        // convert chunk i+1 from staging (1-s) into B tile of stage (1-s)
        if (i + 1 < NCH) {
            const float* sg = (const float*)(sm + OFF_STG + (1 - s) * STG_SZ);
            char* dstg = sm + (1 - s) * STAGE_BF;
            #pragma unroll
            for (int r = 0; r < 2; r++) {
                const float* sf = sg + cvSrc[r];
                float f[8];
                #pragma unroll
                for (int kk = 0; kk < 8; kk++) f[kk] = sf[kk * 128];
                uint32_t hp[4], lp[4];
                #pragma unroll
                for (int j = 0; j < 4; j++) split_pair(f[2*j], f[2*j+1], hp[j], lp[j]);
                *(uint4*)(dstg + OFF_BH + cvDst[r]) = make_uint4(hp[0], hp[1], hp[2], hp[3]);
                *(uint4*)(dstg + OFF_BL + cvDst[r]) = make_uint4(lp[0], lp[1], lp[2], lp[3]);
            }
        }
        // compute stage s (R9 schedule)
        #pragma unroll
        for (int ks = 0; ks < 2; ks++) {
            uint32_t bh[2][4], bl[2][4];
            #pragma unroll
            for (int ng = 0; ng < 2; ng++) {
                LDM_X4(bh[ng], stS + OFF_BH + bLB + ng * (16 * ROWB) + ks * 32);
                LDM_X4(bl[ng], stS + OFF_BL + bLB + ng * (16 * ROWB) + ks * 32);
            }
            #pragma unroll
            for (int mt = 0; mt < 4; mt++) {
                uint32_t ah[4], al[4];
                LDM_X4(ah, stS + OFF_AH + aLB + mt * (16 * ROWB) + ks * 32);
                LDM_X4(al, stS + OFF_AL + aLB + mt * (16 * ROWB) + ks * 32);
                #pragma unroll
                for (int ng = 0; ng < 2; ng++)
                    #pragma unroll
                    for (int h2 = 0; h2 < 2; h2++) {
                        int nt = ng * 2 + h2;
                        MMA_BF16(acc[mt][nt], ah, bh[ng][2*h2], bh[ng][2*h2+1]);
                        MMA_BF16(acc[mt][nt], al, bh[ng][2*h2], bh[ng][2*h2+1]);
                        MMA_BF16(acc[mt][nt], ah, bl[ng][2*h2], bl[ng][2*h2+1]);
                    }
            }
        }
        CP_WAIT0();
        __syncthreads();
    }

    // epilogue: d0=u, d1=v for the same h-col, in-register SwiGLU
    #pragma unroll
    for (int mt = 0; mt < 4; mt++)
        #pragma unroll
        for (int nt = 0; nt < 4; nt++) {
            int j = wn * 16 + nt * 4 + (lane & 3);
            #pragma unroll
            for (int rr = 0; rr < 2; rr++) {
                int r  = wm * 64 + mt * 16 + (lane >> 2) + rr * 8;
                int gm = m0 + r;
                float u = acc[mt][nt][2*rr], v = acc[mt][nt][2*rr+1];
                float h = u / (1.f + __expf(-u)) * v;
                __nv_bfloat16 hh = __float2bfloat16(h);
                __nv_bfloat16 hl = __float2bfloat16(h - __bfloat162float(hh));
                if (gm < cnt) {
                    size_t dst = (size_t)(base + gm) * HID_ + n0 + j;
                    g_hh[dst] = hh;
                    g_hl[dst] = hl;
                }
            }
        }
}

// ---------------------------------------------------------------------------
// GEMM2: y = h @ w2 (3-term split). Same staged pipeline; CTA 128 x 128.
// ---------------------------------------------------------------------------
__global__ void __launch_bounds__(256, 2) ffn2_kernel(const float* __restrict__ w2) {
    const int e   = blockIdx.z;
    const int cnt = g_cnt[e];
    const int m0  = blockIdx.x * 128;
    if (m0 >= cnt) return;
    const int n0   = blockIdx.y * 128;
    const int base = g_off[e];

    extern __shared__ char sm[];
    const uint32_t sbase = smem_u32(sm);
    const int tid = threadIdx.x, lane = tid & 31, wid = tid >> 5;
    const int wm = wid & 1, wn = wid >> 1;

    const float* w2e = w2 + (size_t)e * HID_ * DIM_;

    const __nv_bfloat16* apA[4];
    uint32_t aoA[4];
    #pragma unroll
    for (int q = 0; q < 4; q++) {
        int idx = tid + q * 256;
        int mat = idx >> 9;
        int rem = idx & 511;
        int row = rem >> 2, kq = rem & 3;
        int r   = base + min(m0 + row, cnt - 1);
        apA[q] = (mat ? g_hl : g_hh) + (size_t)r * HID_ + kq * 8;
        aoA[q] = mat * TILE_A + row * ROWB + kq * 16;
    }
    const float* spB[4];
    uint32_t soB[4];
    #pragma unroll
    for (int q = 0; q < 4; q++) {
        int c = tid + q * 256;
        int kr = c >> 5;
        int nq = c & 31;
        spB[q] = w2e + (size_t)kr * DIM_ + (n0 + nq * 4);
        soB[q] = OFF_STG + kr * 512 + nq * 16;
    }
    int cvSrc[2];
    uint32_t cvDst[2];
    #pragma unroll
    for (int r = 0; r < 2; r++) {
        int task = tid + r * 256;
        int np = task & 127;
        int kb = task >> 7;
        cvSrc[r] = kb * 8 * 128 + np;
        cvDst[r] = np * ROWB + kb * 16;
    }

    const int mi = lane >> 3, lr = lane & 7;
    const uint32_t aLB = (uint32_t)((wm * 64 + (mi & 1) * 8 + lr) * ROWB + (mi >> 1) * 16);
    const uint32_t bLB = (uint32_t)((wn * 32 + (mi >> 1) * 8 + lr) * ROWB + (mi & 1) * 16);

    float acc[4][4][4];
    #pragma unroll
    for (int a = 0; a < 4; a++)
        #pragma unroll
        for (int b = 0; b < 4; b++)
            #pragma unroll
            for (int c = 0; c < 4; c++) acc[a][b][c] = 0.f;

    const int NCH = HID_ / 32;   // 176
    #pragma unroll
    for (int q = 0; q < 4; q++) CP_ASYNC16(sbase + aoA[q], apA[q]);
    #pragma unroll
    for (int q = 0; q < 4; q++) CP_ASYNC16(sbase + soB[q], spB[q]);
    CP_COMMIT();
    #pragma unroll
    for (int q = 0; q < 4; q++) CP_ASYNC16(sbase + soB[q] + STG_SZ, spB[q] + (size_t)32 * DIM_);
    CP_COMMIT();
    CP_WAIT1();
    __syncthreads();
    #pragma unroll
    for (int r = 0; r < 2; r++) {
        const float* sf = (const float*)(sm + OFF_STG) + cvSrc[r];
        float f[8];
        #pragma unroll
        for (int kk = 0; kk < 8; kk++) f[kk] = sf[kk * 128];
        uint32_t hp[4], lp[4];
        #pragma unroll
        for (int j = 0; j < 4; j++) split_pair(f[2*j], f[2*j+1], hp[j], lp[j]);
        *(uint4*)(sm + OFF_BH + cvDst[r]) = make_uint4(hp[0], hp[1], hp[2], hp[3]);
        *(uint4*)(sm + OFF_BL + cvDst[r]) = make_uint4(lp[0], lp[1], lp[2], lp[3]);
    }
    CP_WAIT0();
    __syncthreads();

    for (int i = 0; i < NCH; i++) {
        const int s = i & 1;
        const uint32_t stS = sbase + s * STAGE_BF;
        if (i + 1 < NCH) {
            int kk = (i + 1) * 32;
            #pragma unroll
            for (int q = 0; q < 4; q++)
                CP_ASYNC16(sbase + (1 - s) * STAGE_BF + aoA[q], apA[q] + kk);
        }
        if (i + 2 < NCH) {
            size_t kk = (size_t)(i + 2) * 32;
            #pragma unroll
            for (int q = 0; q < 4; q++)
                CP_ASYNC16(sbase + soB[q] + s * STG_SZ, spB[q] + kk * DIM_);
        }
        CP_COMMIT();
        if (i + 1 < NCH) {
            const float* sg = (const float*)(sm + OFF_STG + (1 - s) * STG_SZ);
            char* dstg = sm + (1 - s) * STAGE_BF;
            #pragma unroll
            for (int r = 0; r < 2; r++) {
                const float* sf = sg + cvSrc[r];
                float f[8];
                #pragma unroll
                for (int kk = 0; kk < 8; kk++) f[kk] = sf[kk * 128];
                uint32_t hp[4], lp[4];
                #pragma unroll
                for (int j = 0; j < 4; j++) split_pair(f[2*j], f[2*j+1], hp[j], lp[j]);
                *(uint4*)(dstg + OFF_BH + cvDst[r]) = make_uint4(hp[0], hp[1], hp[2], hp[3]);
                *(uint4*)(dstg + OFF_BL + cvDst[r]) = make_uint4(lp[0], lp[1], lp[2], lp[3]);
            }
        }
        #pragma unroll
        for (int ks = 0; ks < 2; ks++) {
            uint32_t bh[2][4], bl[2][4];
            #pragma unroll
            for (int ng = 0; ng < 2; ng++) {
                LDM_X4(bh[ng], stS + OFF_BH + bLB + ng * (16 * ROWB) + ks * 32);
                LDM_X4(bl[ng], stS + OFF_BL + bLB + ng * (16 * ROWB) + ks * 32);
            }
            #pragma unroll
            for (int mt = 0; mt < 4; mt++) {
                uint32_t ah[4], al[4];
                LDM_X4(ah, stS + OFF_AH + aLB + mt * (16 * ROWB) + ks * 32);
                LDM_X4(al, stS + OFF_AL + aLB + mt * (16 * ROWB) + ks * 32);
                #pragma unroll
                for (int ng = 0; ng < 2; ng++)
                    #pragma unroll
                    for (int h2 = 0; h2 < 2; h2++) {
                        int nt = ng * 2 + h2;
                        MMA_BF16(acc[mt][nt], ah, bh[ng][2*h2], bh[ng][2*h2+1]);
                        MMA_BF16(acc[mt][nt], al, bh[ng][2*h2], bh[ng][2*h2+1]);
                        MMA_BF16(acc[mt][nt], ah, bl[ng][2*h2], bl[ng][2*h2+1]);
                    }
            }
        }
        CP_WAIT0();
        __syncthreads();
    }

    #pragma unroll
    for (int mt = 0; mt < 4; mt++)
        #pragma unroll
        for (int nt = 0; nt < 4; nt++) {
            int c = wn * 32 + nt * 8 + (lane & 3) * 2;
            #pragma unroll
            for (int rr = 0; rr < 2; rr++) {
                int r  = wm * 64 + mt * 16 + (lane >> 2) + rr * 8;
                int gm = m0 + r;
                if (gm < cnt) {
                    size_t dst = (size_t)(base + gm) * DIM_ + n0 + c;
                    *(float2*)(g_y + dst) = make_float2(acc[mt][nt][2*rr], acc[mt][nt][2*rr+1]);
                }
            }
        }
}

// ---------------------------------------------------------------------------
// Combine
// ---------------------------------------------------------------------------
__global__ void combine_kernel(float* __restrict__ out) {
    const int t  = blockIdx.x;
    const int e0 = g_eid[t][0];
    const int e1 = g_eid[t][1];
    const int n0 = g_off[e0] + g_pos[t][0];
    const int n1 = g_off[e1] + g_pos[t][1];
    const float w0 = g_ew[t][0];
    const float w1 = g_ew[t][1];
    const float* y0 = &g_y[(size_t)n0 * DIM_];
    const float* y1 = &g_y[(size_t)n1 * DIM_];
    float* op = out + (size_t)t * DIM_;
    for (int d = threadIdx.x * 4; d < DIM_; d += blockDim.x * 4) {
        float4 a = *(const float4*)(y0 + d);
        float4 b = *(const float4*)(y1 + d);
        *(float4*)(op + d) = make_float4(w0 * a.x + w1 * b.x, w0 * a.y + w1 * b.y,
                                         w0 * a.z + w1 * b.z, w0 * a.w + w1 * b.w);
    }
}

// ---------------------------------------------------------------------------
// Entry point
// ---------------------------------------------------------------------------
extern "C" void kernel_launch(void* const* d_in, const int* in_sizes, int n_in,
                              void* d_out, int out_size) {
    const float* x  = (const float*)d_in[0];
    const float* gw = (const float*)d_in[1];
    const float* w1 = (const float*)d_in[2];
    const float* w2 = (const float*)d_in[3];
    const float* w3 = (const float*)d_in[4];
    float* out = (float*)d_out;

    cudaFuncSetAttribute(ffn1_kernel, cudaFuncAttributeMaxDynamicSharedMemorySize, SMEM_TOT);
    cudaFuncSetAttribute(ffn2_kernel, cudaFuncAttributeMaxDynamicSharedMemorySize, SMEM_TOT);

    gate_kernel<<<T_TOKENS, 256>>>(x, gw);
    route_kernel<<<1, 256>>>();
    split_x_kernel<<<(T_TOKENS * DIM_ / 4) / 256, 256>>>(x);
    ffn1_kernel<<<dim3(T_TOKENS / 128, HID_ / 64, NEXP), 256, SMEM_TOT>>>(w1, w3);
    ffn2_kernel<<<dim3(T_TOKENS / 128, DIM_ / 128, NEXP), 256, SMEM_TOT>>>(w2);
    combine_kernel<<<T_TOKENS, 256>>>(out);
}

// round 13
// speedup vs baseline: 1.1338x; 1.0001x over previous
#include <cuda_runtime.h>
#include <cuda_bf16.h>
#include <cstdint>

#define T_TOKENS 2048
#define DIM_     2048
#define HID_     5632
#define NEXP     8
#define NENT     (T_TOKENS * 2)

// ---------------------------------------------------------------------------
// Scratch (device globals — no cudaMalloc allowed)
// ---------------------------------------------------------------------------
__device__ int   g_eid [T_TOKENS][2];
__device__ float g_ew  [T_TOKENS][2];
__device__ int   g_pos [T_TOKENS][2];
__device__ int   g_list[NEXP][T_TOKENS];
__device__ int   g_cnt [NEXP];
__device__ int   g_off [NEXP];
__device__ __nv_bfloat16 g_xhi[(size_t)T_TOKENS * DIM_];
__device__ __nv_bfloat16 g_xlo[(size_t)T_TOKENS * DIM_];
__device__ __nv_bfloat16 g_hh [(size_t)NENT * HID_];
__device__ __nv_bfloat16 g_hl [(size_t)NENT * HID_];
__device__ float         g_y  [(size_t)NENT * DIM_];

// ---------------------------------------------------------------------------
// Helpers
// ---------------------------------------------------------------------------
__device__ __forceinline__ uint32_t smem_u32(const void* p) {
    uint32_t a;
    asm("{ .reg .u64 t; cvta.to.shared.u64 t, %1; cvt.u32.u64 %0, t; }" : "=r"(a) : "l"(p));
    return a;
}
__device__ __forceinline__ uint32_t pkbf(__nv_bfloat16 a, __nv_bfloat16 b) {
    return (uint32_t)__bfloat16_as_ushort(a) | ((uint32_t)__bfloat16_as_ushort(b) << 16);
}
__device__ __forceinline__ void split_pair(float f0, float f1, uint32_t& hp, uint32_t& lp) {
    __nv_bfloat16 h0 = __float2bfloat16(f0);
    __nv_bfloat16 h1 = __float2bfloat16(f1);
    __nv_bfloat16 l0 = __float2bfloat16(f0 - __bfloat162float(h0));
    __nv_bfloat16 l1 = __float2bfloat16(f1 - __bfloat162float(h1));
    hp = pkbf(h0, h1);
    lp = pkbf(l0, l1);
}

#define LDM_X4(r, addr)                                                          \
    asm volatile("ldmatrix.sync.aligned.m8n8.x4.shared.b16 {%0,%1,%2,%3}, [%4];" \
        : "=r"((r)[0]), "=r"((r)[1]), "=r"((r)[2]), "=r"((r)[3]) : "r"(addr))

#define MMA_BF16(d, a, b0, b1)                                                   \
    asm volatile("mma.sync.aligned.m16n8k16.row.col.f32.bf16.bf16.f32 "          \
        "{%0,%1,%2,%3}, {%4,%5,%6,%7}, {%8,%9}, {%0,%1,%2,%3};"                  \
        : "+f"((d)[0]), "+f"((d)[1]), "+f"((d)[2]), "+f"((d)[3])                 \
        : "r"((a)[0]), "r"((a)[1]), "r"((a)[2]), "r"((a)[3]), "r"(b0), "r"(b1))

#define CP_ASYNC16(dst, src)                                                     \
    asm volatile("cp.async.cg.shared.global [%0], [%1], 16;" :: "r"(dst), "l"(src))
#define CP_COMMIT() asm volatile("cp.async.commit_group;" ::: "memory")
#define CP_WAIT0()  asm volatile("cp.async.wait_group 0;" ::: "memory")
#define CP_WAIT1()  asm volatile("cp.async.wait_group 1;" ::: "memory")

// bf16 tiles: rows of 32 bf16 padded to 80B -> conflict-free ldmatrix (R4-R9)
#define ROWB     80
#define TILE_A   10240          // 128 rows * 80B (one A matrix: hi or lo)
#define OFF_AH   0
#define OFF_AL   10240
#define OFF_BH   20480          // B: 128 rows * 80B per matrix
#define OFF_BL   30720
#define STAGE_BF 40960          // one bf16 stage (A hi/lo + B hi/lo)
// fp32 B staging: 32 k-rows x 128 floats (512B pitch), double-buffered
#define OFF_STG  81920
#define STG_SZ   16384
#define SMEM_TOT 114688         // = 14*8192 exactly; 2 CTAs/SM

// ---------------------------------------------------------------------------
// Gating + routing + x split
// ---------------------------------------------------------------------------
__global__ void gate_kernel(const float* __restrict__ x, const float* __restrict__ gw) {
    const int t = blockIdx.x, lane = threadIdx.x & 31, w = threadIdx.x >> 5;
    const float* xr = x + (size_t)t * DIM_;
    const float* gr = gw + (size_t)w * DIM_;
    float s = 0.f;
    for (int d = lane * 4; d < DIM_; d += 128) {
        float4 a = *(const float4*)(xr + d);
        float4 b = *(const float4*)(gr + d);
        s += a.x * b.x + a.y * b.y + a.z * b.z + a.w * b.w;
    }
    #pragma unroll
    for (int o = 16; o; o >>= 1) s += __shfl_xor_sync(0xffffffffu, s, o);
    __shared__ float sc[NEXP];
    if (lane == 0) sc[w] = s;
    __syncthreads();
    if (threadIdx.x == 0) {
        int b0 = 0; float s0 = sc[0];
        #pragma unroll
        for (int e = 1; e < NEXP; e++) if (sc[e] > s0) { s0 = sc[e]; b0 = e; }
        int b1 = -1; float s1 = -1e30f;
        #pragma unroll
        for (int e = 0; e < NEXP; e++) if (e != b0 && sc[e] > s1) { s1 = sc[e]; b1 = e; }
        float e1 = __expf(s1 - s0);
        float inv = 1.f / (1.f + e1);
        g_eid[t][0] = b0; g_eid[t][1] = b1;
        g_ew [t][0] = inv; g_ew [t][1] = e1 * inv;
    }
}

__global__ void route_kernel() {
    const int lane = threadIdx.x & 31, e = threadIdx.x >> 5;
    if (e < NEXP) {
        int cnt = 0;
        for (int t0 = 0; t0 < T_TOKENS; t0 += 32) {
            int t = t0 + lane;
            int e0 = g_eid[t][0], e1 = g_eid[t][1];
            bool sel = (e0 == e) || (e1 == e);
            int slot = (e0 == e) ? 0 : 1;
            unsigned m = __ballot_sync(0xffffffffu, sel);
            if (sel) {
                int p = cnt + __popc(m & ((1u << lane) - 1u));
                g_list[e][p] = t;
                g_pos[t][slot] = p;
            }
            cnt += __popc(m);
        }
        if (lane == 0) g_cnt[e] = cnt;
    }
    __syncthreads();
    if (threadIdx.x == 0) {
        int off = 0;
        #pragma unroll
        for (int i = 0; i < NEXP; i++) { g_off[i] = off; off += g_cnt[i]; }
    }
}

__global__ void split_x_kernel(const float* __restrict__ x) {
    int i = blockIdx.x * blockDim.x + threadIdx.x;
    float4 v = ((const float4*)x)[i];
    size_t o = (size_t)i * 4;
    float vv[4] = {v.x, v.y, v.z, v.w};
    #pragma unroll
    for (int k = 0; k < 4; k++) {
        __nv_bfloat16 h = __float2bfloat16(vv[k]);
        g_xhi[o + k] = h;
        g_xlo[o + k] = __float2bfloat16(vv[k] - __bfloat162float(h));
    }
}

// ---------------------------------------------------------------------------
// GEMM1: u = x@w1, v = x@w3 (3-term bf16 split), h = silu(u)*v
// 256 threads = 8 warps (2m x 4n), warp tile 64x32, CTA 128 x 64 h-cols
// (128 interleaved B rows). B weights: cp.async fp32 -> staging (2 chunks
// ahead) -> LDS+convert+STS into next stage's bf16 tile (no global latency
// on the barrier path). A: cp.async bf16 at distance 1. One barrier/iter.
// ---------------------------------------------------------------------------
__global__ void __launch_bounds__(256, 2) ffn1_kernel(const float* __restrict__ w1,
                                                      const float* __restrict__ w3) {
    const int e   = blockIdx.z;
    const int cnt = g_cnt[e];
    const int m0  = blockIdx.x * 128;
    if (m0 >= cnt) return;
    const int n0   = blockIdx.y * 64;     // h-cols
    const int base = g_off[e];

    extern __shared__ char sm[];
    const uint32_t sbase = smem_u32(sm);
    const int tid = threadIdx.x, lane = tid & 31, wid = tid >> 5;
    const int wm = wid & 1, wn = wid >> 1;

    const float* w1e = w1 + (size_t)e * DIM_ * HID_;
    const float* w3e = w3 + (size_t)e * DIM_ * HID_;

    // A loader: 1024 chunks (2 mats x 128 rows x 4 kq), 4/thread
    const __nv_bfloat16* apA[4];
    uint32_t aoA[4];
    #pragma unroll
    for (int q = 0; q < 4; q++) {
        int idx = tid + q * 256;
        int mat = idx >> 9;
        int rem = idx & 511;
        int row = rem >> 2, kq = rem & 3;
        int tok = g_list[e][min(m0 + row, cnt - 1)];
        apA[q] = (mat ? g_xlo : g_xhi) + (size_t)tok * DIM_ + kq * 8;
        aoA[q] = mat * TILE_A + row * ROWB + kq * 16;
    }
    // Staging cp loader: 1024 16B-chunks (32 k x 2 mats x 16 quads), 4/thread
    const float* spB[4];
    uint32_t soB[4];
    #pragma unroll
    for (int q = 0; q < 4; q++) {
        int c = tid + q * 256;
        int kr = c >> 5;
        int rem = c & 31;
        int mat = rem >> 4;
        int nq = rem & 15;
        spB[q] = (mat ? w3e : w1e) + (size_t)kr * HID_ + (n0 + nq * 4);
        soB[q] = OFF_STG + kr * 512 + mat * 256 + nq * 16;
    }
    // Converter: 512 tasks (128 interleaved rows x 4 k-blocks), 2/thread
    int cvSrc[2];     // float index base in staging (add kk*128)
    uint32_t cvDst[2];// byte offset within stage (add OFF_BH/OFF_BL)
    #pragma unroll
    for (int r = 0; r < 2; r++) {
        int task = tid + r * 256;
        int np = task & 127;
        int kb = task >> 7;
        cvSrc[r] = kb * 8 * 128 + (np & 1) * 64 + (np >> 1);
        cvDst[r] = np * ROWB + kb * 16;
    }

    const int mi = lane >> 3, lr = lane & 7;
    const uint32_t aLB = (uint32_t)((wm * 64 + (mi & 1) * 8 + lr) * ROWB + (mi >> 1) * 16);
    const uint32_t bLB = (uint32_t)((wn * 32 + (mi >> 1) * 8 + lr) * ROWB + (mi & 1) * 16);

    float acc[4][4][4];
    #pragma unroll
    for (int a = 0; a < 4; a++)
        #pragma unroll
        for (int b = 0; b < 4; b++)
            #pragma unroll
            for (int c = 0; c < 4; c++) acc[a][b][c] = 0.f;

    const int NCH = DIM_ / 32;   // 64
    // prologue: A(0)+S(0) as group1; S(1) as group2
    #pragma unroll
    for (int q = 0; q < 4; q++) CP_ASYNC16(sbase + aoA[q], apA[q]);
    #pragma unroll
    for (int q = 0; q < 4; q++) CP_ASYNC16(sbase + soB[q], spB[q]);
    CP_COMMIT();
    #pragma unroll
    for (int q = 0; q < 4; q++) CP_ASYNC16(sbase + soB[q] + STG_SZ, spB[q] + (size_t)32 * HID_);
    CP_COMMIT();
    CP_WAIT1();
    __syncthreads();
    // convert chunk 0: staging0 -> B tile of stage 0
    #pragma unroll
    for (int r = 0; r < 2; r++) {
        const float* sf = (const float*)(sm + OFF_STG) + cvSrc[r];
        float f[8];
        #pragma unroll
        for (int kk = 0; kk < 8; kk++) f[kk] = sf[kk * 128];
        uint32_t hp[4], lp[4];
        #pragma unroll
        for (int j = 0; j < 4; j++) split_pair(f[2*j], f[2*j+1], hp[j], lp[j]);
        *(uint4*)(sm + OFF_BH + cvDst[r]) = make_uint4(hp[0], hp[1], hp[2], hp[3]);
        *(uint4*)(sm + OFF_BL + cvDst[r]) = make_uint4(lp[0], lp[1], lp[2], lp[3]);
    }
    CP_WAIT0();
    __syncthreads();

    for (int i = 0; i < NCH; i++) {
        const int s = i & 1;
        const uint32_t stS = sbase + s * STAGE_BF;
        // issue copies: A(i+1) into other stage; staging chunk i+2 into buf s
        if (i + 1 < NCH) {
            int kk = (i + 1) * 32;
            #pragma unroll
            for (int q = 0; q < 4; q++)
                CP_ASYNC16(sbase + (1 - s) * STAGE_BF + aoA[q], apA[q] + kk);
        }
        if (i + 2 < NCH) {
            size_t kk = (size_t)(i + 2) * 32;
            #pragma unroll
            for (int q = 0; q < 4; q++)
                CP_ASYNC16(sbase + soB[q] + s * STG_SZ, spB[q] + kk * HID_);
        }
        CP_COMMIT();
        // convert chunk i+1 from staging (1-s) into B tile of stage (1-s)
        if (i + 1 < NCH) {
            const float* sg = (const float*)(sm + OFF_STG + (1 - s) * STG_SZ);
            char* dstg = sm + (1 - s) * STAGE_BF;
            #pragma unroll
            for (int r = 0; r < 2; r++) {
                const float* sf = sg + cvSrc[r];
                float f[8];
                #pragma unroll
                for (int kk = 0; kk < 8; kk++) f[kk] = sf[kk * 128];
                uint32_t hp[4], lp[4];
                #pragma unroll
                for (int j = 0; j < 4; j++) split_pair(f[2*j], f[2*j+1], hp[j], lp[j]);
                *(uint4*)(dstg + OFF_BH + cvDst[r]) = make_uint4(hp[0], hp[1], hp[2], hp[3]);
                *(uint4*)(dstg + OFF_BL + cvDst[r]) = make_uint4(lp[0], lp[1], lp[2], lp[3]);
            }
        }
        // compute stage s (R9 schedule)
        #pragma unroll
        for (int ks = 0; ks < 2; ks++) {
            uint32_t bh[2][4], bl[2][4];
            #pragma unroll
            for (int ng = 0; ng < 2; ng++) {
                LDM_X4(bh[ng], stS + OFF_BH + bLB + ng * (16 * ROWB) + ks * 32);
                LDM_X4(bl[ng], stS + OFF_BL + bLB + ng * (16 * ROWB) + ks * 32);
            }
            #pragma unroll
            for (int mt = 0; mt < 4; mt++) {
                uint32_t ah[4], al[4];
                LDM_X4(ah, stS + OFF_AH + aLB + mt * (16 * ROWB) + ks * 32);
                LDM_X4(al, stS + OFF_AL + aLB + mt * (16 * ROWB) + ks * 32);
                #pragma unroll
                for (int ng = 0; ng < 2; ng++)
                    #pragma unroll
                    for (int h2 = 0; h2 < 2; h2++) {
                        int nt = ng * 2 + h2;
                        MMA_BF16(acc[mt][nt], ah, bh[ng][2*h2], bh[ng][2*h2+1]);
                        MMA_BF16(acc[mt][nt], al, bh[ng][2*h2], bh[ng][2*h2+1]);
                        MMA_BF16(acc[mt][nt], ah, bl[ng][2*h2], bl[ng][2*h2+1]);
                    }
            }
        }
        CP_WAIT0();
        __syncthreads();
    }

    // epilogue: d0=u, d1=v for the same h-col, in-register SwiGLU
    #pragma unroll
    for (int mt = 0; mt < 4; mt++)
        #pragma unroll
        for (int nt = 0; nt < 4; nt++) {
            int j = wn * 16 + nt * 4 + (lane & 3);
            #pragma unroll
            for (int rr = 0; rr < 2; rr++) {
                int r  = wm * 64 + mt * 16 + (lane >> 2) + rr * 8;
                int gm = m0 + r;
                float u = acc[mt][nt][2*rr], v = acc[mt][nt][2*rr+1];
                float h = u / (1.f + __expf(-u)) * v;
                __nv_bfloat16 hh = __float2bfloat16(h);
                __nv_bfloat16 hl = __float2bfloat16(h - __bfloat162float(hh));
                if (gm < cnt) {
                    size_t dst = (size_t)(base + gm) * HID_ + n0 + j;
                    g_hh[dst] = hh;
                    g_hl[dst] = hl;
                }
            }
        }
}

// ---------------------------------------------------------------------------
// GEMM2: y = h @ w2 (3-term split). Same staged pipeline; CTA 128 x 128.
// ---------------------------------------------------------------------------
__global__ void __launch_bounds__(256, 2) ffn2_kernel(const float* __restrict__ w2) {
    const int e   = blockIdx.z;
    const int cnt = g_cnt[e];
    const int m0  = blockIdx.x * 128;
    if (m0 >= cnt) return;
    const int n0   = blockIdx.y * 128;
    const int base = g_off[e];

    extern __shared__ char sm[];
    const uint32_t sbase = smem_u32(sm);
    const int tid = threadIdx.x, lane = tid & 31, wid = tid >> 5;
    const int wm = wid & 1, wn = wid >> 1;

    const float* w2e = w2 + (size_t)e * HID_ * DIM_;

    const __nv_bfloat16* apA[4];
    uint32_t aoA[4];
    #pragma unroll
    for (int q = 0; q < 4; q++) {
        int idx = tid + q * 256;
        int mat = idx >> 9;
        int rem = idx & 511;
        int row = rem >> 2, kq = rem & 3;
        int r   = base + min(m0 + row, cnt - 1);
        apA[q] = (mat ? g_hl : g_hh) + (size_t)r * HID_ + kq * 8;
        aoA[q] = mat * TILE_A + row * ROWB + kq * 16;
    }
    const float* spB[4];
    uint32_t soB[4];
    #pragma unroll
    for (int q = 0; q < 4; q++) {
        int c = tid + q * 256;
        int kr = c >> 5;
        int nq = c & 31;
        spB[q] = w2e + (size_t)kr * DIM_ + (n0 + nq * 4);
        soB[q] = OFF_STG + kr * 512 + nq * 16;
    }
    int cvSrc[2];
    uint32_t cvDst[2];
    #pragma unroll
    for (int r = 0; r < 2; r++) {
        int task = tid + r * 256;
        int np = task & 127;
        int kb = task >> 7;
        cvSrc[r] = kb * 8 * 128 + np;
        cvDst[r] = np * ROWB + kb * 16;
    }

    const int mi = lane >> 3, lr = lane & 7;
    const uint32_t aLB = (uint32_t)((wm * 64 + (mi & 1) * 8 + lr) * ROWB + (mi >> 1) * 16);
    const uint32_t bLB = (uint32_t)((wn * 32 + (mi >> 1) * 8 + lr) * ROWB + (mi & 1) * 16);

    float acc[4][4][4];
    #pragma unroll
    for (int a = 0; a < 4; a++)
        #pragma unroll
        for (int b = 0; b < 4; b++)
            #pragma unroll
            for (int c = 0; c < 4; c++) acc[a][b][c] = 0.f;

    const int NCH = HID_ / 32;   // 176
    #pragma unroll
    for (int q = 0; q < 4; q++) CP_ASYNC16(sbase + aoA[q], apA[q]);
    #pragma unroll
    for (int q = 0; q < 4; q++) CP_ASYNC16(sbase + soB[q], spB[q]);
    CP_COMMIT();
    #pragma unroll
    for (int q = 0; q < 4; q++) CP_ASYNC16(sbase + soB[q] + STG_SZ, spB[q] + (size_t)32 * DIM_);
    CP_COMMIT();
    CP_WAIT1();
    __syncthreads();
    #pragma unroll
    for (int r = 0; r < 2; r++) {
        const float* sf = (const float*)(sm + OFF_STG) + cvSrc[r];
        float f[8];
        #pragma unroll
        for (int kk = 0; kk < 8; kk++) f[kk] = sf[kk * 128];
        uint32_t hp[4], lp[4];
        #pragma unroll
        for (int j = 0; j < 4; j++) split_pair(f[2*j], f[2*j+1], hp[j], lp[j]);
        *(uint4*)(sm + OFF_BH + cvDst[r]) = make_uint4(hp[0], hp[1], hp[2], hp[3]);
        *(uint4*)(sm + OFF_BL + cvDst[r]) = make_uint4(lp[0], lp[1], lp[2], lp[3]);
    }
    CP_WAIT0();
    __syncthreads();

    for (int i = 0; i < NCH; i++) {
        const int s = i & 1;
        const uint32_t stS = sbase + s * STAGE_BF;
        if (i + 1 < NCH) {
            int kk = (i + 1) * 32;
            #pragma unroll
            for (int q = 0; q < 4; q++)
                CP_ASYNC16(sbase + (1 - s) * STAGE_BF + aoA[q], apA[q] + kk);
        }
        if (i + 2 < NCH) {
            size_t kk = (size_t)(i + 2) * 32;
            #pragma unroll
            for (int q = 0; q < 4; q++)
                CP_ASYNC16(sbase + soB[q] + s * STG_SZ, spB[q] + kk * DIM_);
        }
        CP_COMMIT();
        if (i + 1 < NCH) {
            const float* sg = (const float*)(sm + OFF_STG + (1 - s) * STG_SZ);
            char* dstg = sm + (1 - s) * STAGE_BF;
            #pragma unroll
            for (int r = 0; r < 2; r++) {
                const float* sf = sg + cvSrc[r];
                float f[8];
                #pragma unroll
                for (int kk = 0; kk < 8; kk++) f[kk] = sf[kk * 128];
                uint32_t hp[4], lp[4];
                #pragma unroll
                for (int j = 0; j < 4; j++) split_pair(f[2*j], f[2*j+1], hp[j], lp[j]);
                *(uint4*)(dstg + OFF_BH + cvDst[r]) = make_uint4(hp[0], hp[1], hp[2], hp[3]);
                *(uint4*)(dstg + OFF_BL + cvDst[r]) = make_uint4(lp[0], lp[1], lp[2], lp[3]);
            }
        }
        #pragma unroll
        for (int ks = 0; ks < 2; ks++) {
            uint32_t bh[2][4], bl[2][4];
            #pragma unroll
            for (int ng = 0; ng < 2; ng++) {
                LDM_X4(bh[ng], stS + OFF_BH + bLB + ng * (16 * ROWB) + ks * 32);
                LDM_X4(bl[ng], stS + OFF_BL + bLB + ng * (16 * ROWB) + ks * 32);
            }
            #pragma unroll
            for (int mt = 0; mt < 4; mt++) {
                uint32_t ah[4], al[4];
                LDM_X4(ah, stS + OFF_AH + aLB + mt * (16 * ROWB) + ks * 32);
                LDM_X4(al, stS + OFF_AL + aLB + mt * (16 * ROWB) + ks * 32);
                #pragma unroll
                for (int ng = 0; ng < 2; ng++)
                    #pragma unroll
                    for (int h2 = 0; h2 < 2; h2++) {
                        int nt = ng * 2 + h2;
                        MMA_BF16(acc[mt][nt], ah, bh[ng][2*h2], bh[ng][2*h2+1]);
                        MMA_BF16(acc[mt][nt], al, bh[ng][2*h2], bh[ng][2*h2+1]);
                        MMA_BF16(acc[mt][nt], ah, bl[ng][2*h2], bl[ng][2*h2+1]);
                    }
            }
        }
        CP_WAIT0();
        __syncthreads();
    }

    #pragma unroll
    for (int mt = 0; mt < 4; mt++)
        #pragma unroll
        for (int nt = 0; nt < 4; nt++) {
            int c = wn * 32 + nt * 8 + (lane & 3) * 2;
            #pragma unroll
            for (int rr = 0; rr < 2; rr++) {
                int r  = wm * 64 + mt * 16 + (lane >> 2) + rr * 8;
                int gm = m0 + r;
                if (gm < cnt) {
                    size_t dst = (size_t)(base + gm) * DIM_ + n0 + c;
                    *(float2*)(g_y + dst) = make_float2(acc[mt][nt][2*rr], acc[mt][nt][2*rr+1]);
                }
            }
        }
}

// ---------------------------------------------------------------------------
// Combine
// ---------------------------------------------------------------------------
__global__ void combine_kernel(float* __restrict__ out) {
    const int t  = blockIdx.x;
    const int e0 = g_eid[t][0];
    const int e1 = g_eid[t][1];
    const int n0 = g_off[e0] + g_pos[t][0];
    const int n1 = g_off[e1] + g_pos[t][1];
    const float w0 = g_ew[t][0];
    const float w1 = g_ew[t][1];
    const float* y0 = &g_y[(size_t)n0 * DIM_];
    const float* y1 = &g_y[(size_t)n1 * DIM_];
    float* op = out + (size_t)t * DIM_;
    for (int d = threadIdx.x * 4; d < DIM_; d += blockDim.x * 4) {
        float4 a = *(const float4*)(y0 + d);
        float4 b = *(const float4*)(y1 + d);
        *(float4*)(op + d) = make_float4(w0 * a.x + w1 * b.x, w0 * a.y + w1 * b.y,
                                         w0 * a.z + w1 * b.z, w0 * a.w + w1 * b.w);
    }
}

// ---------------------------------------------------------------------------
// Entry point
// ---------------------------------------------------------------------------
extern "C" void kernel_launch(void* const* d_in, const int* in_sizes, int n_in,
                              void* d_out, int out_size) {
    const float* x  = (const float*)d_in[0];
    const float* gw = (const float*)d_in[1];
    const float* w1 = (const float*)d_in[2];
    const float* w2 = (const float*)d_in[3];
    const float* w3 = (const float*)d_in[4];
    float* out = (float*)d_out;

    cudaFuncSetAttribute(ffn1_kernel, cudaFuncAttributeMaxDynamicSharedMemorySize, SMEM_TOT);
    cudaFuncSetAttribute(ffn2_kernel, cudaFuncAttributeMaxDynamicSharedMemorySize, SMEM_TOT);

    gate_kernel<<<T_TOKENS, 256>>>(x, gw);
    route_kernel<<<1, 256>>>();
    split_x_kernel<<<(T_TOKENS * DIM_ / 4) / 256, 256>>>(x);
    ffn1_kernel<<<dim3(T_TOKENS / 128, HID_ / 64, NEXP), 256, SMEM_TOT>>>(w1, w3);
    ffn2_kernel<<<dim3(T_TOKENS / 128, DIM_ / 128, NEXP), 256, SMEM_TOT>>>(w2);
    combine_kernel<<<T_TOKENS, 256>>>(out);
}